// round 1
// baseline (speedup 1.0000x reference)
#include <cuda_runtime.h>

#define SQ 4096
#define HD 256
#define NHEAD 6
#define H3 768

// ---------------- scratch (static __device__ — no allocation) ----------------
__device__ float g_x[SQ * HD];                      // embedded tokens
__device__ float g_q[NHEAD * SQ * HD];
__device__ float g_k[NHEAD * SQ * HD];
__device__ float g_v[NHEAD * SQ * HD];
__device__ float g_scores[(size_t)NHEAD * SQ * SQ]; // 402 MB
__device__ float g_ocat[SQ * NHEAD * HD];           // concat layout [s][h*H+e]
__device__ float g_yo[SQ * HD];                     // attn projection out
__device__ float g_y[SQ * HD];                      // post-LN
__device__ float g_gi[SQ * H3];                     // y @ W_ih^T + b_ih
__device__ float g_hbuf[2 * HD];                    // GRU h double buffer
__device__ unsigned g_cnt;                          // GRU inter-CTA barrier

// ---------------- packed f32x2 helpers (Blackwell dual-rate fp32) ------------
__device__ __forceinline__ unsigned long long pack2f(float x) {
    unsigned long long r;
    asm("mov.b64 %0, {%1, %1};" : "=l"(r) : "f"(x));
    return r;
}
__device__ __forceinline__ void ffma2(unsigned long long& d,
                                      unsigned long long a,
                                      unsigned long long b) {
    asm("fma.rn.f32x2 %0, %1, %2, %3;" : "=l"(d) : "l"(a), "l"(b), "l"(d));
}

// ---------------- embedding gather ----------------
__global__ void embed_kernel(const int* __restrict__ tok,
                             const float* __restrict__ emb) {
    int s = blockIdx.x, t = threadIdx.x;
    g_x[s * HD + t] = emb[(long long)tok[s] * HD + t];
}

// ---------------- SGEMM: C = alpha * A*B(^T) (+bias), batched over z ---------
// BM=BN=128, BK=16, 256 threads, 8x8 per thread, f32x2 packed accumulators.
// All of M % 128, N % 128, K % 16 hold for every call site (no predication).
template <bool TRANSB, bool HASBIAS>
__global__ __launch_bounds__(256)
void sgemm_kernel(int M, int N, int K,
                  const float* __restrict__ A, int lda, long long sA,
                  const float* __restrict__ B, int ldb, long long sB,
                  const float* __restrict__ bias, int sBias,
                  float* __restrict__ C, int ldc, long long sC,
                  float alpha) {
    __shared__ float As[16][132];
    __shared__ float Bs[16][132];

    int z = blockIdx.z;
    A += (long long)z * sA;
    B += (long long)z * sB;
    C += (long long)z * sC;
    const float* bp = HASBIAS ? (bias + (long long)z * sBias) : nullptr;

    int tid = threadIdx.x;
    int tx = tid & 15, ty = tid >> 4;
    int brow = blockIdx.y * 128, bcol = blockIdx.x * 128;

    int lrow = tid >> 1;        // 0..127
    int lcb  = (tid & 1) * 8;   // 0 or 8
    int bkr  = tid >> 4;        // 0..15  (NN B loader)
    int bcb  = (tid & 15) * 8;  // 0..120

    unsigned long long acc[8][4];
#pragma unroll
    for (int i = 0; i < 8; i++)
#pragma unroll
        for (int j = 0; j < 4; j++) acc[i][j] = 0ull;

    for (int k0 = 0; k0 < K; k0 += 16) {
        // A tile 128x16 -> As[k][m]
        const float* ap = A + (long long)(brow + lrow) * lda + k0 + lcb;
        float4 a0 = *(const float4*)ap;
        float4 a1 = *(const float4*)(ap + 4);
        As[lcb + 0][lrow] = a0.x; As[lcb + 1][lrow] = a0.y;
        As[lcb + 2][lrow] = a0.z; As[lcb + 3][lrow] = a0.w;
        As[lcb + 4][lrow] = a1.x; As[lcb + 5][lrow] = a1.y;
        As[lcb + 6][lrow] = a1.z; As[lcb + 7][lrow] = a1.w;
        if (TRANSB) {
            const float* bpt = B + (long long)(bcol + lrow) * ldb + k0 + lcb;
            float4 b0 = *(const float4*)bpt;
            float4 b1 = *(const float4*)(bpt + 4);
            Bs[lcb + 0][lrow] = b0.x; Bs[lcb + 1][lrow] = b0.y;
            Bs[lcb + 2][lrow] = b0.z; Bs[lcb + 3][lrow] = b0.w;
            Bs[lcb + 4][lrow] = b1.x; Bs[lcb + 5][lrow] = b1.y;
            Bs[lcb + 6][lrow] = b1.z; Bs[lcb + 7][lrow] = b1.w;
        } else {
            const float* bpt = B + (long long)(k0 + bkr) * ldb + bcol + bcb;
            *(float4*)&Bs[bkr][bcb]     = *(const float4*)bpt;
            *(float4*)&Bs[bkr][bcb + 4] = *(const float4*)(bpt + 4);
        }
        __syncthreads();
#pragma unroll
        for (int kk = 0; kk < 16; kk++) {
            float av[8];
            *(float4*)&av[0] = *(const float4*)&As[kk][ty * 8];
            *(float4*)&av[4] = *(const float4*)&As[kk][ty * 8 + 4];
            unsigned long long bq[4];
            bq[0] = *(const unsigned long long*)&Bs[kk][tx * 8];
            bq[1] = *(const unsigned long long*)&Bs[kk][tx * 8 + 2];
            bq[2] = *(const unsigned long long*)&Bs[kk][tx * 8 + 4];
            bq[3] = *(const unsigned long long*)&Bs[kk][tx * 8 + 6];
#pragma unroll
            for (int i = 0; i < 8; i++) {
                unsigned long long apk = pack2f(av[i]);
                ffma2(acc[i][0], apk, bq[0]);
                ffma2(acc[i][1], apk, bq[1]);
                ffma2(acc[i][2], apk, bq[2]);
                ffma2(acc[i][3], apk, bq[3]);
            }
        }
        __syncthreads();
    }

    float bb[8];
    if (HASBIAS) {
        *(float4*)&bb[0] = *(const float4*)&bp[bcol + tx * 8];
        *(float4*)&bb[4] = *(const float4*)&bp[bcol + tx * 8 + 4];
    }
#pragma unroll
    for (int i = 0; i < 8; i++) {
        long long row = brow + ty * 8 + i;
        float* cr = C + row * (long long)ldc + bcol + tx * 8;
        float2 p0 = *reinterpret_cast<float2*>(&acc[i][0]);
        float2 p1 = *reinterpret_cast<float2*>(&acc[i][1]);
        float2 p2 = *reinterpret_cast<float2*>(&acc[i][2]);
        float2 p3 = *reinterpret_cast<float2*>(&acc[i][3]);
        float4 o0, o1;
        o0.x = p0.x * alpha; o0.y = p0.y * alpha;
        o0.z = p1.x * alpha; o0.w = p1.y * alpha;
        o1.x = p2.x * alpha; o1.y = p2.y * alpha;
        o1.z = p3.x * alpha; o1.w = p3.y * alpha;
        if (HASBIAS) {
            o0.x += bb[0]; o0.y += bb[1]; o0.z += bb[2]; o0.w += bb[3];
            o1.x += bb[4]; o1.y += bb[5]; o1.z += bb[6]; o1.w += bb[7];
        }
        *(float4*)cr = o0;
        *(float4*)(cr + 4) = o1;
    }
}

// ---------------- row softmax over 4096 cols (one block per row) -------------
__global__ __launch_bounds__(256) void softmax_kernel(float* __restrict__ P) {
    __shared__ float sm[8];
    __shared__ float bc;
    long long base = (long long)blockIdx.x * SQ;
    float4* p4 = (float4*)(P + base);
    int tid = threadIdx.x;

    float4 v[4];
#pragma unroll
    for (int i = 0; i < 4; i++) v[i] = p4[tid + 256 * i];

    float m = -1e30f;
#pragma unroll
    for (int i = 0; i < 4; i++) {
        m = fmaxf(m, fmaxf(fmaxf(v[i].x, v[i].y), fmaxf(v[i].z, v[i].w)));
    }
#pragma unroll
    for (int off = 16; off; off >>= 1)
        m = fmaxf(m, __shfl_xor_sync(0xffffffffu, m, off));
    if ((tid & 31) == 0) sm[tid >> 5] = m;
    __syncthreads();
    if (tid == 0) {
        float t = sm[0];
#pragma unroll
        for (int j = 1; j < 8; j++) t = fmaxf(t, sm[j]);
        bc = t;
    }
    __syncthreads();
    m = bc;

    float s = 0.f;
#pragma unroll
    for (int i = 0; i < 4; i++) {
        v[i].x = __expf(v[i].x - m); v[i].y = __expf(v[i].y - m);
        v[i].z = __expf(v[i].z - m); v[i].w = __expf(v[i].w - m);
        s += v[i].x + v[i].y + v[i].z + v[i].w;
    }
#pragma unroll
    for (int off = 16; off; off >>= 1)
        s += __shfl_xor_sync(0xffffffffu, s, off);
    __syncthreads();
    if ((tid & 31) == 0) sm[tid >> 5] = s;
    __syncthreads();
    if (tid == 0) {
        float t = 0.f;
#pragma unroll
        for (int j = 0; j < 8; j++) t += sm[j];
        bc = 1.0f / t;
    }
    __syncthreads();
    float inv = bc;
#pragma unroll
    for (int i = 0; i < 4; i++) {
        v[i].x *= inv; v[i].y *= inv; v[i].z *= inv; v[i].w *= inv;
        p4[tid + 256 * i] = v[i];
    }
}

// ---------------- residual + LayerNorm (one block per row, H=256) ------------
__global__ __launch_bounds__(256) void addln_kernel(const float* __restrict__ lng,
                                                    const float* __restrict__ lnb) {
    __shared__ float sm[8];
    __shared__ float bc;
    int s = blockIdx.x, t = threadIdx.x;
    float v = g_x[s * HD + t] + g_yo[s * HD + t];

    float a = v;
#pragma unroll
    for (int off = 16; off; off >>= 1) a += __shfl_xor_sync(0xffffffffu, a, off);
    if ((t & 31) == 0) sm[t >> 5] = a;
    __syncthreads();
    if (t == 0) {
        float tt = 0.f;
#pragma unroll
        for (int j = 0; j < 8; j++) tt += sm[j];
        bc = tt * (1.0f / HD);
    }
    __syncthreads();
    float mu = bc;
    float d = v - mu;
    float q = d * d;
    __syncthreads();
#pragma unroll
    for (int off = 16; off; off >>= 1) q += __shfl_xor_sync(0xffffffffu, q, off);
    if ((t & 31) == 0) sm[t >> 5] = q;
    __syncthreads();
    if (t == 0) {
        float tt = 0.f;
#pragma unroll
        for (int j = 0; j < 8; j++) tt += sm[j];
        bc = tt * (1.0f / HD);
    }
    __syncthreads();
    float var = bc;
    g_y[s * HD + t] = d * rsqrtf(var + 1e-5f) * lng[t] + lnb[t];
}

// ---------------- GRU barrier reset ----------------
__global__ void reset_kernel() {
    if (threadIdx.x == 0) g_cnt = 0u;
    if (threadIdx.x < 2 * HD) g_hbuf[threadIdx.x] = 0.0f;
}

// ---------------- persistent multi-CTA GRU scan ----------------
// 8 CTAs x 1024 threads. CTA b owns hidden indices [b*32, b*32+32).
// Warp w handles hidden index i = b*32 + w; lane l holds W_hh[{i,256+i,512+i}][8l..8l+7]
// in registers (24 regs). Global-memory counter barrier + double-buffered h.
__global__ __launch_bounds__(1024, 1)
void gru_kernel(const float* __restrict__ gi,
                const float* __restrict__ Whh,
                const float* __restrict__ bhh) {
    __shared__ float hs[HD];
    int tid = threadIdx.x;
    int w = tid >> 5, l = tid & 31;
    int i = blockIdx.x * 32 + w;

    float wr[8], wz[8], wn[8];
    {
        const float4* r4 = (const float4*)(Whh + (long long)i * HD + l * 8);
        float4 t0 = r4[0], t1 = r4[1];
        wr[0] = t0.x; wr[1] = t0.y; wr[2] = t0.z; wr[3] = t0.w;
        wr[4] = t1.x; wr[5] = t1.y; wr[6] = t1.z; wr[7] = t1.w;
        const float4* z4 = (const float4*)(Whh + (long long)(HD + i) * HD + l * 8);
        t0 = z4[0]; t1 = z4[1];
        wz[0] = t0.x; wz[1] = t0.y; wz[2] = t0.z; wz[3] = t0.w;
        wz[4] = t1.x; wz[5] = t1.y; wz[6] = t1.z; wz[7] = t1.w;
        const float4* n4 = (const float4*)(Whh + (long long)(2 * HD + i) * HD + l * 8);
        t0 = n4[0]; t1 = n4[1];
        wn[0] = t0.x; wn[1] = t0.y; wn[2] = t0.z; wn[3] = t0.w;
        wn[4] = t1.x; wn[5] = t1.y; wn[6] = t1.z; wn[7] = t1.w;
    }
    float br = 0.f, bz = 0.f, bn = 0.f;
    if (l == 0) { br = bhh[i]; bz = bhh[HD + i]; bn = bhh[2 * HD + i]; }

    if (tid < HD) hs[tid] = 0.0f;
    __syncthreads();

    unsigned nblk = gridDim.x;
    for (int t = 0; t < SQ; t++) {
        float gir = 0.f, giz = 0.f, gin = 0.f;
        if (l == 0) {
            const float* gp = gi + (long long)t * H3 + i;
            gir = __ldg(gp); giz = __ldg(gp + HD); gin = __ldg(gp + 2 * HD);
        }
        float hv[8];
        *(float4*)&hv[0] = *(const float4*)&hs[l * 8];
        *(float4*)&hv[4] = *(const float4*)&hs[l * 8 + 4];
        float dr = 0.f, dz = 0.f, dn = 0.f;
#pragma unroll
        for (int j = 0; j < 8; j++) {
            dr += wr[j] * hv[j];
            dz += wz[j] * hv[j];
            dn += wn[j] * hv[j];
        }
#pragma unroll
        for (int off = 16; off; off >>= 1) {
            dr += __shfl_xor_sync(0xffffffffu, dr, off);
            dz += __shfl_xor_sync(0xffffffffu, dz, off);
            dn += __shfl_xor_sync(0xffffffffu, dn, off);
        }
        if (l == 0) {
            float r = 1.0f / (1.0f + __expf(-(gir + br + dr)));
            float z = 1.0f / (1.0f + __expf(-(giz + bz + dz)));
            float n = tanhf(gin + r * (dn + bn));
            float h2 = (1.0f - z) * n + z * hs[i];
            volatile float* gb = (volatile float*)(g_hbuf + ((t + 1) & 1) * HD);
            gb[i] = h2;
            __threadfence();
        }
        __syncthreads();
        if (tid == 0) {
            __threadfence();
            atomicAdd(&g_cnt, 1u);
            unsigned want = nblk * (unsigned)(t + 1);
            while (*((volatile unsigned*)&g_cnt) < want) { }
        }
        __syncthreads();
        if (tid < HD) {
            hs[tid] = *((volatile float*)(g_hbuf + ((t + 1) & 1) * HD) + tid);
        }
        __syncthreads();
    }
}

// ---------------- output writer (tuple (out, out) flattened) -----------------
__global__ void writeout_kernel(float* __restrict__ out, int n) {
    int i = blockIdx.x * blockDim.x + threadIdx.x;
    if (i < n) out[i] = g_hbuf[i & (HD - 1)];   // final h lives in buffer 0
}

// ---------------- launch ----------------
extern "C" void kernel_launch(void* const* d_in, const int* in_sizes, int n_in,
                              void* d_out, int out_size) {
    const int*   tokens = (const int*)d_in[0];
    const float* emb    = (const float*)d_in[1];
    const float* Wq     = (const float*)d_in[2];
    const float* bq     = (const float*)d_in[3];
    const float* Wk     = (const float*)d_in[4];
    const float* bk     = (const float*)d_in[5];
    const float* Wv     = (const float*)d_in[6];
    const float* bv     = (const float*)d_in[7];
    const float* Wo     = (const float*)d_in[8];
    const float* bo     = (const float*)d_in[9];
    const float* ln_g   = (const float*)d_in[10];
    const float* ln_b   = (const float*)d_in[11];
    const float* W_ih   = (const float*)d_in[12];
    const float* W_hh   = (const float*)d_in[13];
    const float* b_ih   = (const float*)d_in[14];
    const float* b_hh   = (const float*)d_in[15];
    float* out = (float*)d_out;

    float *px, *pq, *pk, *pv, *ps, *po, *pyo, *py, *pgi;
    cudaGetSymbolAddress((void**)&px,  g_x);
    cudaGetSymbolAddress((void**)&pq,  g_q);
    cudaGetSymbolAddress((void**)&pk,  g_k);
    cudaGetSymbolAddress((void**)&pv,  g_v);
    cudaGetSymbolAddress((void**)&ps,  g_scores);
    cudaGetSymbolAddress((void**)&po,  g_ocat);
    cudaGetSymbolAddress((void**)&pyo, g_yo);
    cudaGetSymbolAddress((void**)&py,  g_y);
    cudaGetSymbolAddress((void**)&pgi, g_gi);

    const long long SH = (long long)SQ * HD;
    const long long SS = (long long)SQ * SQ;

    // 1. embed
    embed_kernel<<<SQ, HD>>>(tokens, emb);

    // 2. QKV projections (batched over heads in grid.z)
    dim3 gqkv(2, 32, NHEAD);
    sgemm_kernel<false, true><<<gqkv, 256>>>(SQ, HD, HD, px, HD, 0,
                                             Wq, HD, (long long)HD * HD, bq, HD,
                                             pq, HD, SH, 1.0f);
    sgemm_kernel<false, true><<<gqkv, 256>>>(SQ, HD, HD, px, HD, 0,
                                             Wk, HD, (long long)HD * HD, bk, HD,
                                             pk, HD, SH, 1.0f);
    sgemm_kernel<false, true><<<gqkv, 256>>>(SQ, HD, HD, px, HD, 0,
                                             Wv, HD, (long long)HD * HD, bv, HD,
                                             pv, HD, SH, 1.0f);

    // 3. scores = q @ k^T / 16   (NT, batched over heads)
    dim3 gqk(32, 32, NHEAD);
    sgemm_kernel<true, false><<<gqk, 256>>>(SQ, SQ, HD, pq, HD, SH,
                                            pk, HD, SH, nullptr, 0,
                                            ps, SQ, SS, 1.0f / 16.0f);

    // 4. softmax over last axis
    softmax_kernel<<<NHEAD * SQ, 256>>>(ps);

    // 5. o = P @ v  -> written in concat layout [s][h*256+e]
    dim3 gpv(2, 32, NHEAD);
    sgemm_kernel<false, false><<<gpv, 256>>>(SQ, HD, SQ, ps, SQ, SS,
                                             pv, HD, SH, nullptr, 0,
                                             po, NHEAD * HD, HD, 1.0f);

    // 6. out projection: yo = ocat @ Wo + bo
    dim3 gproj(2, 32, 1);
    sgemm_kernel<false, true><<<gproj, 256>>>(SQ, HD, NHEAD * HD, po, NHEAD * HD, 0,
                                              Wo, HD, 0, bo, 0,
                                              pyo, HD, 0, 1.0f);

    // 7. y = LayerNorm(x + yo)
    addln_kernel<<<SQ, 256>>>(ln_g, ln_b);

    // 8. gi = y @ W_ih^T + b_ih  (NT)
    dim3 ggi(6, 32, 1);
    sgemm_kernel<true, true><<<ggi, 256>>>(SQ, H3, HD, py, HD, 0,
                                           W_ih, HD, 0, b_ih, 0,
                                           pgi, H3, 0, 1.0f);

    // 9. GRU scan (8 persistent CTAs, register-resident W_hh)
    reset_kernel<<<1, 512>>>();
    gru_kernel<<<8, 1024>>>(pgi, W_hh, b_hh);

    // 10. write output
    writeout_kernel<<<(out_size + 255) / 256, 256>>>(out, out_size);
}

// round 2
// speedup vs baseline: 1.5130x; 1.5130x over previous
#include <cuda_runtime.h>

#define SQ 4096
#define HD 256
#define NHEAD 6
#define H3 768

// ---------------- scratch (static __device__ — no allocation) ----------------
__device__ float g_x[SQ * HD];                      // embedded tokens
__device__ float g_q[NHEAD * SQ * HD];
__device__ float g_k[NHEAD * SQ * HD];
__device__ float g_v[NHEAD * SQ * HD];
__device__ float g_scores[(size_t)NHEAD * SQ * SQ]; // 402 MB
__device__ float g_ocat[SQ * NHEAD * HD];           // concat layout [s][h*H+e]
__device__ float g_yo[SQ * HD];                     // attn projection out
__device__ float g_y[SQ * HD];                      // post-LN
__device__ float g_gi[SQ * H3];                     // y @ W_ih^T + b_ih

// ---------------- packed f32x2 helpers (Blackwell dual-rate fp32) ------------
__device__ __forceinline__ unsigned long long pack2f(float x) {
    unsigned long long r;
    asm("mov.b64 %0, {%1, %1};" : "=l"(r) : "f"(x));
    return r;
}
__device__ __forceinline__ void ffma2(unsigned long long& d,
                                      unsigned long long a,
                                      unsigned long long b) {
    asm("fma.rn.f32x2 %0, %1, %2, %3;" : "=l"(d) : "l"(a), "l"(b), "l"(d));
}
__device__ __forceinline__ unsigned smem_u32(const void* p) {
    unsigned r;
    asm("{ .reg .u64 t; cvta.to.shared.u64 t, %1; cvt.u32.u64 %0, t; }"
        : "=r"(r) : "l"(p));
    return r;
}
__device__ __forceinline__ unsigned mapa_rank(unsigned addr, unsigned rank) {
    unsigned r;
    asm("mapa.shared::cluster.u32 %0, %1, %2;" : "=r"(r) : "r"(addr), "r"(rank));
    return r;
}
__device__ __forceinline__ void st_cluster_f32(unsigned addr, float v) {
    asm volatile("st.shared::cluster.f32 [%0], %1;" :: "r"(addr), "f"(v) : "memory");
}
__device__ __forceinline__ unsigned my_ctarank() {
    unsigned r;
    asm("mov.u32 %0, %%cluster_ctarank;" : "=r"(r));
    return r;
}

// ---------------- embedding gather ----------------
__global__ void embed_kernel(const int* __restrict__ tok,
                             const float* __restrict__ emb) {
    int s = blockIdx.x, t = threadIdx.x;
    g_x[s * HD + t] = emb[(long long)tok[s] * HD + t];
}

// ---------------- SGEMM: C = alpha * A*B(^T) (+bias), batched over z ---------
// BM=BN=128, BK=16, 256 threads, 8x8 per thread, f32x2 packed accumulators,
// 2-stage smem double buffering (one __syncthreads per k-tile).
template <bool TRANSB, bool HASBIAS>
__global__ __launch_bounds__(256, 2)
void sgemm_kernel(int M, int N, int K,
                  const float* __restrict__ A, int lda, long long sA,
                  const float* __restrict__ B, int ldb, long long sB,
                  const float* __restrict__ bias, int sBias,
                  float* __restrict__ C, int ldc, long long sC,
                  float alpha) {
    __shared__ float As[2][16][132];
    __shared__ float Bs[2][16][132];

    int z = blockIdx.z;
    A += (long long)z * sA;
    B += (long long)z * sB;
    C += (long long)z * sC;
    const float* bp = HASBIAS ? (bias + (long long)z * sBias) : nullptr;

    int tid = threadIdx.x;
    int tx = tid & 15, ty = tid >> 4;
    int brow = blockIdx.y * 128, bcol = blockIdx.x * 128;

    int lrow = tid >> 1;        // 0..127
    int lcb  = (tid & 1) * 8;   // 0 or 8
    int bkr  = tid >> 4;        // 0..15  (NN B loader)
    int bcb  = (tid & 15) * 8;  // 0..120

    unsigned long long acc[8][4];
#pragma unroll
    for (int i = 0; i < 8; i++)
#pragma unroll
        for (int j = 0; j < 4; j++) acc[i][j] = 0ull;

    float4 na0, na1, nb0, nb1;

    // ---- tile loaders (global -> registers) ----
    auto LOADG = [&](int k0) {
        const float* ap = A + (long long)(brow + lrow) * lda + k0 + lcb;
        na0 = *(const float4*)ap;
        na1 = *(const float4*)(ap + 4);
        if (TRANSB) {
            const float* bpt = B + (long long)(bcol + lrow) * ldb + k0 + lcb;
            nb0 = *(const float4*)bpt;
            nb1 = *(const float4*)(bpt + 4);
        } else {
            const float* bpt = B + (long long)(k0 + bkr) * ldb + bcol + bcb;
            nb0 = *(const float4*)bpt;
            nb1 = *(const float4*)(bpt + 4);
        }
    };
    auto STORES = [&](int buf) {
        As[buf][lcb + 0][lrow] = na0.x; As[buf][lcb + 1][lrow] = na0.y;
        As[buf][lcb + 2][lrow] = na0.z; As[buf][lcb + 3][lrow] = na0.w;
        As[buf][lcb + 4][lrow] = na1.x; As[buf][lcb + 5][lrow] = na1.y;
        As[buf][lcb + 6][lrow] = na1.z; As[buf][lcb + 7][lrow] = na1.w;
        if (TRANSB) {
            Bs[buf][lcb + 0][lrow] = nb0.x; Bs[buf][lcb + 1][lrow] = nb0.y;
            Bs[buf][lcb + 2][lrow] = nb0.z; Bs[buf][lcb + 3][lrow] = nb0.w;
            Bs[buf][lcb + 4][lrow] = nb1.x; Bs[buf][lcb + 5][lrow] = nb1.y;
            Bs[buf][lcb + 6][lrow] = nb1.z; Bs[buf][lcb + 7][lrow] = nb1.w;
        } else {
            *(float4*)&Bs[buf][bkr][bcb]     = nb0;
            *(float4*)&Bs[buf][bkr][bcb + 4] = nb1;
        }
    };

    LOADG(0);
    STORES(0);
    __syncthreads();

    int buf = 0;
    for (int k0 = 0; k0 < K; k0 += 16) {
        bool has_next = (k0 + 16) < K;
        if (has_next) LOADG(k0 + 16);
#pragma unroll
        for (int kk = 0; kk < 16; kk++) {
            float av[8];
            *(float4*)&av[0] = *(const float4*)&As[buf][kk][ty * 8];
            *(float4*)&av[4] = *(const float4*)&As[buf][kk][ty * 8 + 4];
            unsigned long long bq[4];
            bq[0] = *(const unsigned long long*)&Bs[buf][kk][tx * 8];
            bq[1] = *(const unsigned long long*)&Bs[buf][kk][tx * 8 + 2];
            bq[2] = *(const unsigned long long*)&Bs[buf][kk][tx * 8 + 4];
            bq[3] = *(const unsigned long long*)&Bs[buf][kk][tx * 8 + 6];
#pragma unroll
            for (int i = 0; i < 8; i++) {
                unsigned long long apk = pack2f(av[i]);
                ffma2(acc[i][0], apk, bq[0]);
                ffma2(acc[i][1], apk, bq[1]);
                ffma2(acc[i][2], apk, bq[2]);
                ffma2(acc[i][3], apk, bq[3]);
            }
        }
        if (has_next) {
            STORES(buf ^ 1);
            __syncthreads();
            buf ^= 1;
        }
    }

    float bb[8];
    if (HASBIAS) {
        *(float4*)&bb[0] = *(const float4*)&bp[bcol + tx * 8];
        *(float4*)&bb[4] = *(const float4*)&bp[bcol + tx * 8 + 4];
    }
#pragma unroll
    for (int i = 0; i < 8; i++) {
        long long row = brow + ty * 8 + i;
        float* cr = C + row * (long long)ldc + bcol + tx * 8;
        float2 p0 = *reinterpret_cast<float2*>(&acc[i][0]);
        float2 p1 = *reinterpret_cast<float2*>(&acc[i][1]);
        float2 p2 = *reinterpret_cast<float2*>(&acc[i][2]);
        float2 p3 = *reinterpret_cast<float2*>(&acc[i][3]);
        float4 o0, o1;
        o0.x = p0.x * alpha; o0.y = p0.y * alpha;
        o0.z = p1.x * alpha; o0.w = p1.y * alpha;
        o1.x = p2.x * alpha; o1.y = p2.y * alpha;
        o1.z = p3.x * alpha; o1.w = p3.y * alpha;
        if (HASBIAS) {
            o0.x += bb[0]; o0.y += bb[1]; o0.z += bb[2]; o0.w += bb[3];
            o1.x += bb[4]; o1.y += bb[5]; o1.z += bb[6]; o1.w += bb[7];
        }
        *(float4*)cr = o0;
        *(float4*)(cr + 4) = o1;
    }
}

// ---------------- row softmax over 4096 cols (one block per row) -------------
__global__ __launch_bounds__(256) void softmax_kernel(float* __restrict__ P) {
    __shared__ float sm[8];
    __shared__ float bc;
    long long base = (long long)blockIdx.x * SQ;
    float4* p4 = (float4*)(P + base);
    int tid = threadIdx.x;

    float4 v[4];
#pragma unroll
    for (int i = 0; i < 4; i++) v[i] = p4[tid + 256 * i];

    float m = -1e30f;
#pragma unroll
    for (int i = 0; i < 4; i++) {
        m = fmaxf(m, fmaxf(fmaxf(v[i].x, v[i].y), fmaxf(v[i].z, v[i].w)));
    }
#pragma unroll
    for (int off = 16; off; off >>= 1)
        m = fmaxf(m, __shfl_xor_sync(0xffffffffu, m, off));
    if ((tid & 31) == 0) sm[tid >> 5] = m;
    __syncthreads();
    if (tid == 0) {
        float t = sm[0];
#pragma unroll
        for (int j = 1; j < 8; j++) t = fmaxf(t, sm[j]);
        bc = t;
    }
    __syncthreads();
    m = bc;

    float s = 0.f;
#pragma unroll
    for (int i = 0; i < 4; i++) {
        v[i].x = __expf(v[i].x - m); v[i].y = __expf(v[i].y - m);
        v[i].z = __expf(v[i].z - m); v[i].w = __expf(v[i].w - m);
        s += v[i].x + v[i].y + v[i].z + v[i].w;
    }
#pragma unroll
    for (int off = 16; off; off >>= 1)
        s += __shfl_xor_sync(0xffffffffu, s, off);
    __syncthreads();
    if ((tid & 31) == 0) sm[tid >> 5] = s;
    __syncthreads();
    if (tid == 0) {
        float t = 0.f;
#pragma unroll
        for (int j = 0; j < 8; j++) t += sm[j];
        bc = 1.0f / t;
    }
    __syncthreads();
    float inv = bc;
#pragma unroll
    for (int i = 0; i < 4; i++) {
        v[i].x *= inv; v[i].y *= inv; v[i].z *= inv; v[i].w *= inv;
        p4[tid + 256 * i] = v[i];
    }
}

// ---------------- residual + LayerNorm (one block per row, H=256) ------------
__global__ __launch_bounds__(256) void addln_kernel(const float* __restrict__ lng,
                                                    const float* __restrict__ lnb) {
    __shared__ float sm[8];
    __shared__ float bc;
    int s = blockIdx.x, t = threadIdx.x;
    float v = g_x[s * HD + t] + g_yo[s * HD + t];

    float a = v;
#pragma unroll
    for (int off = 16; off; off >>= 1) a += __shfl_xor_sync(0xffffffffu, a, off);
    if ((t & 31) == 0) sm[t >> 5] = a;
    __syncthreads();
    if (t == 0) {
        float tt = 0.f;
#pragma unroll
        for (int j = 0; j < 8; j++) tt += sm[j];
        bc = tt * (1.0f / HD);
    }
    __syncthreads();
    float mu = bc;
    float d = v - mu;
    float q = d * d;
    __syncthreads();
#pragma unroll
    for (int off = 16; off; off >>= 1) q += __shfl_xor_sync(0xffffffffu, q, off);
    if ((t & 31) == 0) sm[t >> 5] = q;
    __syncthreads();
    if (t == 0) {
        float tt = 0.f;
#pragma unroll
        for (int j = 0; j < 8; j++) tt += sm[j];
        bc = tt * (1.0f / HD);
    }
    __syncthreads();
    float var = bc;
    g_y[s * HD + t] = d * rsqrtf(var + 1e-5f) * lng[t] + lnb[t];
}

// ---------------- cluster GRU scan ----------------
// 8-CTA cluster, 1024 threads each. CTA rank b owns hidden indices
// [b*32, b*32+32) — warp w computes index i = b*32 + w; lane l holds
// W_hh[{i,256+i,512+i}][8l..8l+7] in registers (24 regs/thread).
// h exchange: lanes 0..7 store the new h value directly into all 8 CTAs'
// SMEM (mapa + st.shared::cluster), double-buffered; one cluster barrier
// per step provides release/acquire ordering.
__global__ void __cluster_dims__(8, 1, 1) __launch_bounds__(1024, 1)
gru_cluster_kernel(const float* __restrict__ gi,
                   const float* __restrict__ Whh,
                   const float* __restrict__ bhh,
                   float* __restrict__ out, int out_n) {
    __shared__ float hs[2][HD];
    int tid = threadIdx.x;
    int w = tid >> 5, l = tid & 31;
    unsigned rank = my_ctarank();
    int i = (int)rank * 32 + w;

    // register-resident W_hh slices
    float wr[8], wz[8], wn[8];
    {
        const float4* r4 = (const float4*)(Whh + (long long)i * HD + l * 8);
        float4 t0 = r4[0], t1 = r4[1];
        wr[0] = t0.x; wr[1] = t0.y; wr[2] = t0.z; wr[3] = t0.w;
        wr[4] = t1.x; wr[5] = t1.y; wr[6] = t1.z; wr[7] = t1.w;
        const float4* z4 = (const float4*)(Whh + (long long)(HD + i) * HD + l * 8);
        t0 = z4[0]; t1 = z4[1];
        wz[0] = t0.x; wz[1] = t0.y; wz[2] = t0.z; wz[3] = t0.w;
        wz[4] = t1.x; wz[5] = t1.y; wz[6] = t1.z; wz[7] = t1.w;
        const float4* n4 = (const float4*)(Whh + (long long)(2 * HD + i) * HD + l * 8);
        t0 = n4[0]; t1 = n4[1];
        wn[0] = t0.x; wn[1] = t0.y; wn[2] = t0.z; wn[3] = t0.w;
        wn[4] = t1.x; wn[5] = t1.y; wn[6] = t1.z; wn[7] = t1.w;
    }
    float br = 0.f, bz = 0.f, bn = 0.f;
    if (l == 0) { br = bhh[i]; bz = bhh[HD + i]; bn = bhh[2 * HD + i]; }

    // precompute remote store addresses for this warp's h slot (lanes 0..7)
    unsigned hb = smem_u32(&hs[0][0]);
    unsigned ra0 = 0, ra1 = 0;
    if (l < 8) {
        ra0 = mapa_rank(hb + (unsigned)i * 4u, (unsigned)l);
        ra1 = mapa_rank(hb + (unsigned)(HD + i) * 4u, (unsigned)l);
    }

    if (tid < HD) { hs[0][tid] = 0.0f; hs[1][tid] = 0.0f; }
    asm volatile("barrier.cluster.arrive.aligned;" ::: "memory");
    asm volatile("barrier.cluster.wait.aligned;" ::: "memory");

    // prefetch gi for t=0 (lane 0 of each warp)
    float gir = 0.f, giz = 0.f, gin = 0.f;
    if (l == 0) {
        const float* gp = gi + i;
        gir = __ldg(gp); giz = __ldg(gp + HD); gin = __ldg(gp + 2 * HD);
    }

    for (int t = 0; t < SQ; t++) {
        int cur = t & 1;
        float hv[8];
        *(float4*)&hv[0] = *(const float4*)&hs[cur][l * 8];
        *(float4*)&hv[4] = *(const float4*)&hs[cur][l * 8 + 4];
        float dr = 0.f, dz = 0.f, dn = 0.f;
#pragma unroll
        for (int j = 0; j < 8; j++) {
            dr += wr[j] * hv[j];
            dz += wz[j] * hv[j];
            dn += wn[j] * hv[j];
        }
#pragma unroll
        for (int off = 16; off; off >>= 1) {
            dr += __shfl_xor_sync(0xffffffffu, dr, off);
            dz += __shfl_xor_sync(0xffffffffu, dz, off);
            dn += __shfl_xor_sync(0xffffffffu, dn, off);
        }
        float h2 = 0.f;
        if (l == 0) {
            float hprev = hs[cur][i];
            float r = 1.0f / (1.0f + __expf(-(gir + br + dr)));
            float z = 1.0f / (1.0f + __expf(-(giz + bz + dz)));
            float n = tanhf(gin + r * (dn + bn));
            h2 = (1.0f - z) * n + z * hprev;
        }
        h2 = __shfl_sync(0xffffffffu, h2, 0);
        // prefetch next step's gi while the barrier drains
        if (l == 0 && t + 1 < SQ) {
            const float* gp = gi + (long long)(t + 1) * H3 + i;
            gir = __ldg(gp); giz = __ldg(gp + HD); gin = __ldg(gp + 2 * HD);
        }
        if (l < 8) {
            st_cluster_f32(((t + 1) & 1) ? ra1 : ra0, h2);
        }
        asm volatile("barrier.cluster.arrive.aligned;" ::: "memory");
        asm volatile("barrier.cluster.wait.aligned;" ::: "memory");
    }

    // final h is in hs[0] (step SQ-1 wrote buffer SQ&1 == 0)
    if (rank == 0) {
        for (int idx = tid; idx < out_n; idx += 1024)
            out[idx] = hs[0][idx & (HD - 1)];
    }
}

// ---------------- launch ----------------
extern "C" void kernel_launch(void* const* d_in, const int* in_sizes, int n_in,
                              void* d_out, int out_size) {
    const int*   tokens = (const int*)d_in[0];
    const float* emb    = (const float*)d_in[1];
    const float* Wq     = (const float*)d_in[2];
    const float* bq     = (const float*)d_in[3];
    const float* Wk     = (const float*)d_in[4];
    const float* bk     = (const float*)d_in[5];
    const float* Wv     = (const float*)d_in[6];
    const float* bv     = (const float*)d_in[7];
    const float* Wo     = (const float*)d_in[8];
    const float* bo     = (const float*)d_in[9];
    const float* ln_g   = (const float*)d_in[10];
    const float* ln_b   = (const float*)d_in[11];
    const float* W_ih   = (const float*)d_in[12];
    const float* W_hh   = (const float*)d_in[13];
    const float* b_ih   = (const float*)d_in[14];
    const float* b_hh   = (const float*)d_in[15];
    float* out = (float*)d_out;

    float *px, *pq, *pk, *pv, *ps, *po, *pyo, *py, *pgi;
    cudaGetSymbolAddress((void**)&px,  g_x);
    cudaGetSymbolAddress((void**)&pq,  g_q);
    cudaGetSymbolAddress((void**)&pk,  g_k);
    cudaGetSymbolAddress((void**)&pv,  g_v);
    cudaGetSymbolAddress((void**)&ps,  g_scores);
    cudaGetSymbolAddress((void**)&po,  g_ocat);
    cudaGetSymbolAddress((void**)&pyo, g_yo);
    cudaGetSymbolAddress((void**)&py,  g_y);
    cudaGetSymbolAddress((void**)&pgi, g_gi);

    const long long SH = (long long)SQ * HD;
    const long long SS = (long long)SQ * SQ;

    // 1. embed
    embed_kernel<<<SQ, HD>>>(tokens, emb);

    // 2. QKV projections (batched over heads in grid.z)
    dim3 gqkv(2, 32, NHEAD);
    sgemm_kernel<false, true><<<gqkv, 256>>>(SQ, HD, HD, px, HD, 0,
                                             Wq, HD, (long long)HD * HD, bq, HD,
                                             pq, HD, SH, 1.0f);
    sgemm_kernel<false, true><<<gqkv, 256>>>(SQ, HD, HD, px, HD, 0,
                                             Wk, HD, (long long)HD * HD, bk, HD,
                                             pk, HD, SH, 1.0f);
    sgemm_kernel<false, true><<<gqkv, 256>>>(SQ, HD, HD, px, HD, 0,
                                             Wv, HD, (long long)HD * HD, bv, HD,
                                             pv, HD, SH, 1.0f);

    // 3. scores = q @ k^T / 16   (NT, batched over heads)
    dim3 gqk(32, 32, NHEAD);
    sgemm_kernel<true, false><<<gqk, 256>>>(SQ, SQ, HD, pq, HD, SH,
                                            pk, HD, SH, nullptr, 0,
                                            ps, SQ, SS, 1.0f / 16.0f);

    // 4. softmax over last axis
    softmax_kernel<<<NHEAD * SQ, 256>>>(ps);

    // 5. o = P @ v  -> written in concat layout [s][h*256+e]
    dim3 gpv(2, 32, NHEAD);
    sgemm_kernel<false, false><<<gpv, 256>>>(SQ, HD, SQ, ps, SQ, SS,
                                             pv, HD, SH, nullptr, 0,
                                             po, NHEAD * HD, HD, 1.0f);

    // 6. out projection: yo = ocat @ Wo + bo
    dim3 gproj(2, 32, 1);
    sgemm_kernel<false, true><<<gproj, 256>>>(SQ, HD, NHEAD * HD, po, NHEAD * HD, 0,
                                              Wo, HD, 0, bo, 0,
                                              pyo, HD, 0, 1.0f);

    // 7. y = LayerNorm(x + yo)
    addln_kernel<<<SQ, 256>>>(ln_g, ln_b);

    // 8. gi = y @ W_ih^T + b_ih  (NT)
    dim3 ggi(6, 32, 1);
    sgemm_kernel<true, true><<<ggi, 256>>>(SQ, H3, HD, py, HD, 0,
                                           W_ih, HD, 0, b_ih, 0,
                                           pgi, H3, 0, 1.0f);

    // 9. cluster GRU scan (8-CTA cluster, register-resident W_hh, DSMEM h exchange)
    gru_cluster_kernel<<<8, 1024>>>(pgi, W_hh, b_hh, out, out_size);
}